// round 16
// baseline (speedup 1.0000x reference)
#include <cuda_runtime.h>
#include <math.h>

#define NQ 10
#define NP 100
#define FD 256
#define NOUT 30
#define TWO_PI_F 6.2831853071795864769f

// Cross-CTA scratch + per-sample arrival counters (zero-init; the combining
// CTA resets its counter each launch so graph replays see clean state).
__device__ float g_mres[3][256][32];
__device__ int   g_cnt[256];

// Pair barrier for cross-warp exchange on amp-bit b (7/8/9). Partners:
// b=7 -> warp^1, b=8 -> warp^2, b=9 -> warp^4. Disjoint id ranges per bit.
__device__ __forceinline__ void pbar(int b, int warp) {
    int id;
    if (b == 7)      id = 1 + (warp >> 1);
    else if (b == 8) id = 5 + ((warp & 1) | ((warp & 4) >> 1));
    else             id = 9 + (warp & 3);
    asm volatile("bar.sync %0, 64;" :: "r"(id) : "memory");
}

// ---------------------------------------------------------------------------
// One CTA = one (sample, branch). 256 threads, 4 amps/thread.
// amp = (tid << 2) | j : j bits 0-1 local, tid bits 0-4 lane (amp bits 2-6),
// tid bits 5-7 cross-warp (amp bits 7-9, via pair-barrier smem exchange).
// ---------------------------------------------------------------------------

__device__ __forceinline__ void apply_u(int b, float u00r, float u00i,
                                        float u01r, float u01i,
                                        float ar[4], float ai[4],
                                        int tid, int warp, float* B) {
    if (b < 2) {                                  // local register pairs
#pragma unroll
        for (int t = 0; t < 2; t++) {
            int j0 = (b == 0) ? t * 2 : t;
            int j1 = j0 | (1 << b);
            float r0 = ar[j0], i0 = ai[j0], r1 = ar[j1], i1 = ai[j1];
            ar[j0] =  u00r * r0 - u00i * i0 + u01r * r1 - u01i * i1;
            ai[j0] =  u00r * i0 + u00i * r0 + u01r * i1 + u01i * r1;
            ar[j1] = -u01r * r0 - u01i * i0 + u00r * r1 + u00i * i1;
            ai[j1] = -u01r * i0 + u01i * r0 + u00r * i1 - u00i * r1;
        }
    } else if (b < 7) {                           // lane bits: warp shuffle
        const int m = 1 << (b - 2);
        const int s = (tid >> (b - 2)) & 1;
        const float cwr = u00r, cwi = s ? -u00i : u00i;
        const float cpr = s ? -u01r : u01r, cpi = u01i;
#pragma unroll
        for (int j = 0; j < 4; j++) {
            float pr = __shfl_xor_sync(0xffffffffu, ar[j], m);
            float pi = __shfl_xor_sync(0xffffffffu, ai[j], m);
            float orr = ar[j], oii = ai[j];
            ar[j] = cwr * orr - cwi * oii + cpr * pr - cpi * pi;
            ai[j] = cwr * oii + cwi * orr + cpr * pi + cpi * pr;
        }
    } else {                                      // cross-warp bits: smem pair
        const int m = 1 << (b - 2);
        const int s = (tid >> (b - 2)) & 1;
        float4* A4 = (float4*)B;
        float4* I4 = (float4*)(B + 1024);
        A4[tid] = make_float4(ar[0], ar[1], ar[2], ar[3]);
        I4[tid] = make_float4(ai[0], ai[1], ai[2], ai[3]);
        pbar(b, warp);
        float4 pa = A4[tid ^ m];
        float4 pb = I4[tid ^ m];
        const float cwr = u00r, cwi = s ? -u00i : u00i;
        const float cpr = s ? -u01r : u01r, cpi = u01i;
        float prr[4] = {pa.x, pa.y, pa.z, pa.w};
        float pii[4] = {pb.x, pb.y, pb.z, pb.w};
#pragma unroll
        for (int j = 0; j < 4; j++) {
            float orr = ar[j], oii = ai[j];
            ar[j] = cwr * orr - cwi * oii + cpr * prr[j] - cpi * pii[j];
            ai[j] = cwr * oii + cwi * orr + cpr * pii[j] + cpi * prr[j];
        }
        pbar(b, warp);                            // reads done before reuse
    }
}

__device__ __forceinline__ void apply_crx(int pc, int pt, float c, float s,
                                          float ar[4], float ai[4],
                                          int tid, int warp, float* B) {
    const bool tc = (pc >= 2) ? (((tid >> (pc - 2)) & 1) != 0) : true;
    if (pt < 2) {                                 // local target
#pragma unroll
        for (int t = 0; t < 2; t++) {
            int j0 = (pt == 0) ? t * 2 : t;
            int j1 = j0 | (1 << pt);
            bool upd = tc && (pc < 2 ? (((j0 >> pc) & 1) != 0) : true);
            if (upd) {
                float r0 = ar[j0], i0 = ai[j0], r1 = ar[j1], i1 = ai[j1];
                ar[j0] = c * r0 + s * i1;  ai[j0] = c * i0 - s * r1;
                ar[j1] = c * r1 + s * i0;  ai[j1] = c * i1 - s * r0;
            }
        }
    } else if (pt < 7) {                          // lane target: shuffle
        const int m = 1 << (pt - 2);
        if (pc >= 7 && !tc) return;               // warp-uniform control: skip
#pragma unroll
        for (int j = 0; j < 4; j++) {
            float pr = __shfl_xor_sync(0xffffffffu, ar[j], m);
            float pi = __shfl_xor_sync(0xffffffffu, ai[j], m);
            bool upd = tc && (pc < 2 ? (((j >> pc) & 1) != 0) : true);
            if (upd) {
                float orr = ar[j], oii = ai[j];
                ar[j] = c * orr + s * pi;
                ai[j] = c * oii - s * pr;
            }
        }
    } else {                                      // cross-warp target: smem pair
        const int m = 1 << (pt - 2);
        float4* A4 = (float4*)B;
        float4* I4 = (float4*)(B + 1024);
        A4[tid] = make_float4(ar[0], ar[1], ar[2], ar[3]);
        I4[tid] = make_float4(ai[0], ai[1], ai[2], ai[3]);
        pbar(pt, warp);
        float4 pa = A4[tid ^ m];
        float4 pb = I4[tid ^ m];
        float prr[4] = {pa.x, pa.y, pa.z, pa.w};
        float pii[4] = {pb.x, pb.y, pb.z, pb.w};
#pragma unroll
        for (int j = 0; j < 4; j++) {
            bool upd = tc && (pc < 2 ? (((j >> pc) & 1) != 0) : true);
            if (upd) {
                float orr = ar[j], oii = ai[j];
                ar[j] = c * orr + s * pii[j];
                ai[j] = c * oii - s * prr[j];
            }
        }
        pbar(pt, warp);                           // reads done before reuse
    }
}

__global__ __launch_bounds__(256, 6)
void qsb_kernel(const float* __restrict__ x,
                const float* __restrict__ W1, const float* __restrict__ b1,
                const float* __restrict__ W2, const float* __restrict__ b2,
                const float* __restrict__ W3, const float* __restrict__ b3,
                const float* __restrict__ base1, const float* __restrict__ base2,
                const float* __restrict__ base3,
                const float* __restrict__ alpha_r, const float* __restrict__ alpha_i,
                const float* __restrict__ beta_r,  const float* __restrict__ beta_i,
                const float* __restrict__ gamma_r, const float* __restrict__ gamma_i,
                float* __restrict__ out) {
    __shared__ float sx[FD];
    __shared__ float gc[NP], gs[NP];
    __shared__ float ginit[NQ][4];                // col-0 of fused layer-0 U's
    __shared__ float buf[2048];                   // exchange/dump buffer (also raw GEMV)
    __shared__ float sm30[32];                    // per-CTA expectation values

    const int tid   = threadIdx.x;
    const int batch = blockIdx.x;
    const int g     = blockIdx.y;                 // branch 0..2
    const int lane  = tid & 31;
    const int warp  = tid >> 5;

    sx[tid] = x[batch * FD + tid];

    const float* W  = (g == 0) ? W1 : ((g == 1) ? W2 : W3);
    const float* bb = (g == 0) ? b1 : ((g == 1) ? b2 : b3);
    const float* ba = (g == 0) ? base1 : ((g == 1) ? base2 : base3);
    __syncthreads();

    // ---- GEMV: octet layout (8 lanes/row, 4 rows per warp concurrently) ----
    {
        const int o = lane >> 3;                  // octet 0..3
        const int q = lane & 7;
        const float4* sx4 = (const float4*)sx;
        const float4* Wv  = (const float4*)W;     // 64 float4 per row
        float acc[4];
#pragma unroll
        for (int it = 0; it < 4; it++) {
            const int row = warp + 8 * (4 * it + o);
            float a = 0.f;
            if (row < NP) {
                const float4* Wr = Wv + row * 64 + q * 8;
#pragma unroll
                for (int j = 0; j < 8; j++) {
                    float4 wv = Wr[j];
                    float4 xv = sx4[q * 8 + j];
                    a += wv.x * xv.x + wv.y * xv.y + wv.z * xv.z + wv.w * xv.w;
                }
            }
            acc[it] = a;
        }
#pragma unroll
        for (int off = 4; off; off >>= 1) {
#pragma unroll
            for (int it = 0; it < 4; it++)
                acc[it] += __shfl_xor_sync(0xffffffffu, acc[it], off);
        }
        if (q == 0) {
#pragma unroll
            for (int it = 0; it < 4; it++) {
                const int row = warp + 8 * (4 * it + o);
                if (row < NP) buf[row] = acc[it];
            }
        }
    }
    __syncthreads();
    if (tid < NP) {                               // parallel activations
        float t   = buf[tid] + bb[tid] + ba[tid];
        float sig = 1.f / (1.f + __expf(-t));
        float sv, cv;
        __sincosf(0.5f * sig * TWO_PI_F, &sv, &cv);
        gc[tid] = cv; gs[tid] = sv;
    }
    __syncthreads();

    // ---- layer-0 1q sweep folded into product-state init ----
    if (tid < NQ) {
        const int w = tid, i0 = 3 * w;
        float c0 = gc[i0], s0 = gs[i0];
        float c1 = gc[i0 + 1], s1 = gs[i0 + 1];
        float cz = gc[i0 + 2], sz = gs[i0 + 2];
        float u00r =  cz * c1 * c0 + sz * s1 * s0;
        float u00i =  cz * s1 * s0 - sz * c1 * c0;
        float u01r = -(cz * s1 * c0 + sz * c1 * s0);
        float u01i =  sz * s1 * c0 - cz * c1 * s0;
        ginit[9 - w][0] = u00r;   ginit[9 - w][1] = u00i;   // amp|0>
        ginit[9 - w][2] = -u01r;  ginit[9 - w][3] = u01i;   // amp|1> = -conj(u01)
    }
    __syncthreads();

    // ---- init: product state with fwd-ring gates i=0 (p30) and i=1 (p31)
    //      folded in analytically (partner amps are still product values) ----
    float ar[4], ai[4];
    {
        float Rr = 1.f, Ri = 0.f;                 // product over bits {2..6, 9}
#pragma unroll
        for (int p = 2; p < 10; p++) {
            if (p == 7 || p == 8) continue;
            const int bit = (tid >> (p - 2)) & 1;
            float fr = ginit[p][bit * 2];
            float fi = ginit[p][bit * 2 + 1];
            float nr = Rr * fr - Ri * fi;
            float ni = Rr * fi + Ri * fr;
            Rr = nr; Ri = ni;
        }
        const int b7 = (tid >> 5) & 1;
        const int b8 = (tid >> 6) & 1;
        const int b9 = (tid >> 7) & 1;
        float f7r  = ginit[7][b7 * 2],       f7i  = ginit[7][b7 * 2 + 1];
        float f7nr = ginit[7][(1 - b7) * 2], f7ni = ginit[7][(1 - b7) * 2 + 1];
        float f8r  = ginit[8][b8 * 2],       f8i  = ginit[8][b8 * 2 + 1];
        float f8nr = ginit[8][(1 - b8) * 2], f8ni = ginit[8][(1 - b8) * 2 + 1];
        float R7r  = Rr * f7r  - Ri * f7i,   R7i  = Rr * f7i  + Ri * f7r;
        float R7nr = Rr * f7nr - Ri * f7ni,  R7ni = Rr * f7ni + Ri * f7nr;
        float qbr  = R7r  * f8r  - R7i  * f8i,  qbi  = R7r  * f8i  + R7i  * f8r;
        float q8r  = R7r  * f8nr - R7i  * f8ni, q8i  = R7r  * f8ni + R7i  * f8nr;
        float q7r  = R7nr * f8r  - R7ni * f8i,  q7i  = R7nr * f8i  + R7ni * f8r;
        float q78r = R7nr * f8nr - R7ni * f8ni, q78i = R7nr * f8ni + R7ni * f8nr;
        // gate p30: CRX ctrl bit9, tgt bit8 (RX symmetric: a' = c a - i s a_partner)
        float c0g = gc[30], s0g = gs[30];
        float A1br, A1bi, A1fr, A1fi;
        if (b9) {
            A1br = c0g * qbr + s0g * q8i;   A1bi = c0g * qbi - s0g * q8r;
            A1fr = c0g * q7r + s0g * q78i;  A1fi = c0g * q7i - s0g * q78r;
        } else {
            A1br = qbr; A1bi = qbi; A1fr = q7r; A1fi = q7i;
        }
        // gate p31: CRX ctrl bit8, tgt bit7
        float c1g = gc[31], s1g = gs[31];
        float Sr, Si;
        if (b8) { Sr = c1g * A1br + s1g * A1fi; Si = c1g * A1bi - s1g * A1fr; }
        else    { Sr = A1br; Si = A1bi; }
        // expand local bits 0,1
        float h1r0 = ginit[1][0], h1i0 = ginit[1][1];
        float h1r1 = ginit[1][2], h1i1 = ginit[1][3];
        float h0r0 = ginit[0][0], h0i0 = ginit[0][1];
        float h0r1 = ginit[0][2], h0i1 = ginit[0][3];
        float t0r = Sr * h1r0 - Si * h1i0, t0i = Sr * h1i0 + Si * h1r0;
        float t1r = Sr * h1r1 - Si * h1i1, t1i = Sr * h1i1 + Si * h1r1;
        ar[0] = t0r * h0r0 - t0i * h0i0;  ai[0] = t0r * h0i0 + t0i * h0r0;
        ar[1] = t0r * h0r1 - t0i * h0i1;  ai[1] = t0r * h0i1 + t0i * h0r1;
        ar[2] = t1r * h0r0 - t1i * h0i0;  ai[2] = t1r * h0i0 + t1i * h0r0;
        ar[3] = t1r * h0r1 - t1i * h0i1;  ai[3] = t1r * h0i1 + t1i * h0r1;
    }

    // ---- layer 0 rings: fwd i=2..9 (params 32..39), bwd (40..49) ----
    int idx = 32;
#pragma unroll
    for (int i = 2; i < NQ; i++) {
        apply_crx(9 - i, 9 - ((i + 1) % NQ), gc[idx], gs[idx],
                  ar, ai, tid, warp, buf);
        idx++;
    }
    idx = 40;
#pragma unroll
    for (int i = NQ - 1; i >= 0; i--) {
        apply_crx(9 - i, 9 - ((i + 9) % NQ), gc[idx], gs[idx],
                  ar, ai, tid, warp, buf);
        idx++;
    }

    // ---- layer 1 ----
    {
        float c0 = gc[50], s0 = gs[50];
        float c1 = gc[51], s1 = gs[51];
        float cz = gc[52], sz = gs[52];
        float u00r =  cz * c1 * c0 + sz * s1 * s0;
        float u00i =  cz * s1 * s0 - sz * c1 * c0;
        float u01r = -(cz * s1 * c0 + sz * c1 * s0);
        float u01i =  sz * s1 * c0 - cz * c1 * s0;
        apply_u(9, u00r, u00i, u01r, u01i, ar, ai, tid, warp, buf);
    }
    // Fused forward ring: MCRX(w-1, w) absorbing U_w, w=1..9.
#pragma unroll
    for (int w = 1; w <= 9; w++) {
        const int iu = 50 + 3 * w;
        float c0 = gc[iu], s0 = gs[iu];
        float c1 = gc[iu + 1], s1 = gs[iu + 1];
        float cz = gc[iu + 2], sz = gs[iu + 2];
        float u00r =  cz * c1 * c0 + sz * s1 * s0;
        float u00i =  cz * s1 * s0 - sz * c1 * c0;
        float u01r = -(cz * s1 * c0 + sz * c1 * s0);
        float u01i =  sz * s1 * c0 - cz * c1 * s0;
        float cr = gc[79 + w], sr = gs[79 + w];
        float v00r = cr * u00r + sr * u01i;
        float v00i = cr * u00i + sr * u01r;
        float v01r = cr * u01r - sr * u00i;
        float v01i = cr * u01i - sr * u00r;
        const int pc = 10 - w;
        const int pt = 9 - w;
        if (pc >= 2) {
            const bool tc = ((tid >> (pc - 2)) & 1) != 0;
            float m00r = tc ? v00r : u00r;
            float m00i = tc ? v00i : u00i;
            float m01r = tc ? v01r : u01r;
            float m01i = tc ? v01i : u01i;
            apply_u(pt, m00r, m00i, m01r, m01i, ar, ai, tid, warp, buf);
        } else {
            // w=9: pc=1 (local), pt=0 (local): U on pair(0,1), V on pair(2,3)
            {
                float r0 = ar[0], i0 = ai[0], r1 = ar[1], i1 = ai[1];
                ar[0] =  u00r * r0 - u00i * i0 + u01r * r1 - u01i * i1;
                ai[0] =  u00r * i0 + u00i * r0 + u01r * i1 + u01i * r1;
                ar[1] = -u01r * r0 - u01i * i0 + u00r * r1 + u00i * i1;
                ai[1] = -u01r * i0 + u01i * r0 + u00r * i1 - u00i * r1;
            }
            {
                float r0 = ar[2], i0 = ai[2], r1 = ar[3], i1 = ai[3];
                ar[2] =  v00r * r0 - v00i * i0 + v01r * r1 - v01i * i1;
                ai[2] =  v00r * i0 + v00i * r0 + v01r * i1 + v01i * r1;
                ar[3] = -v01r * r0 - v01i * i0 + v00r * r1 + v00i * i1;
                ai[3] = -v01r * i0 + v01i * r0 + v00r * i1 - v00i * r1;
            }
        }
    }
    // Closing forward-ring gate CRX(9, 0): control bit 0, target bit 9.
    apply_crx(0, 9, gc[89], gs[89], ar, ai, tid, warp, buf);
    // Backward ring, params 90..99
    idx = 90;
#pragma unroll
    for (int i = NQ - 1; i >= 0; i--) {
        apply_crx(9 - i, 9 - ((i + 9) % NQ), gc[idx], gs[idx],
                  ar, ai, tid, warp, buf);
        idx++;
    }

    // ---- dump state ----
    {
        float4* A4 = (float4*)buf;
        float4* I4 = (float4*)(buf + 1024);
        A4[tid] = make_float4(ar[0], ar[1], ar[2], ar[3]);
        I4[tid] = make_float4(ai[0], ai[1], ai[2], ai[3]);
        __syncthreads();
    }

    // ---- expectations: warp w handles wires {w, w+8}; vectorized loads ----
    {
        const float4* A4 = (const float4*)buf;
        const float4* I4 = (const float4*)(buf + 1024);
        for (int wq = warp; wq < NQ; wq += 8) {
            const int p = 9 - wq;
            float zr = 0.f, zi = 0.f, pz = 0.f;
            if (p >= 2) {
#pragma unroll
                for (int it = 0; it < 4; it++) {
                    int k  = it * 128 + lane * 4;
                    int i0 = ((k >> p) << (p + 1)) | (k & ((1 << p) - 1));
                    int v0 = i0 >> 2;
                    int v1 = (i0 | (1 << p)) >> 2;
                    float4 r0 = A4[v0], m0 = I4[v0];
                    float4 r1 = A4[v1], m1 = I4[v1];
                    zr += r0.x * r1.x + m0.x * m1.x + r0.y * r1.y + m0.y * m1.y
                        + r0.z * r1.z + m0.z * m1.z + r0.w * r1.w + m0.w * m1.w;
                    zi += r0.x * m1.x - m0.x * r1.x + r0.y * m1.y - m0.y * r1.y
                        + r0.z * m1.z - m0.z * r1.z + r0.w * m1.w - m0.w * r1.w;
                    pz += r0.x * r0.x + m0.x * m0.x - r1.x * r1.x - m1.x * m1.x
                        + r0.y * r0.y + m0.y * m0.y - r1.y * r1.y - m1.y * m1.y
                        + r0.z * r0.z + m0.z * m0.z - r1.z * r1.z - m1.z * m1.z
                        + r0.w * r0.w + m0.w * m0.w - r1.w * r1.w - m1.w * m1.w;
                }
            } else {
#pragma unroll
                for (int it = 0; it < 8; it++) {
                    int t = it * 32 + lane;
                    float4 fr = A4[t], fi = I4[t];
                    if (p == 0) {                 // pairs (x,y), (z,w)
                        zr += fr.x * fr.y + fi.x * fi.y + fr.z * fr.w + fi.z * fi.w;
                        zi += fr.x * fi.y - fi.x * fr.y + fr.z * fi.w - fi.z * fr.w;
                        pz += fr.x * fr.x + fi.x * fi.x - fr.y * fr.y - fi.y * fi.y
                            + fr.z * fr.z + fi.z * fi.z - fr.w * fr.w - fi.w * fi.w;
                    } else {                      // p==1: pairs (x,z), (y,w)
                        zr += fr.x * fr.z + fi.x * fi.z + fr.y * fr.w + fi.y * fi.w;
                        zi += fr.x * fi.z - fi.x * fr.z + fr.y * fi.w - fi.y * fr.w;
                        pz += fr.x * fr.x + fi.x * fi.x - fr.z * fr.z - fi.z * fi.z
                            + fr.y * fr.y + fi.y * fi.y - fr.w * fr.w - fi.w * fi.w;
                    }
                }
            }
#pragma unroll
            for (int o = 16; o; o >>= 1) {
                zr += __shfl_xor_sync(0xffffffffu, zr, o);
                zi += __shfl_xor_sync(0xffffffffu, zi, o);
                pz += __shfl_xor_sync(0xffffffffu, pz, o);
            }
            if (lane == 0) {
                sm30[wq]          = 2.f * zr;
                sm30[NQ + wq]     = 2.f * zi;
                sm30[2 * NQ + wq] = pz;
            }
        }
    }
    __syncthreads();

    // ---- tail: warp 0 only. store -> release fence -> atomic -> combine ----
    if (warp == 0) {
        if (lane < NOUT) g_mres[g][batch][lane] = sm30[lane];
        __syncwarp();
        __threadfence();                          // release (1 warp only)
        int old = 0;
        if (lane == 0) old = atomicAdd(&g_cnt[batch], 1);
        old = __shfl_sync(0xffffffffu, old, 0);
        if (old == 2) {                           // last branch: combine
            __threadfence();                      // acquire (1 warp only)
            if (lane < NOUT) {
                float arv = alpha_r[0], aiv = alpha_i[0];
                float brv = beta_r[0],  biv = beta_i[0];
                float grv = gamma_r[0], giv = gamma_i[0];
                float nrm = sqrtf(arv * arv + aiv * aiv + brv * brv +
                                  biv * biv + grv * grv + giv * giv + 1e-9f);
                float inv = 1.f / nrm;
                float m0 = g_mres[0][batch][lane];
                float m1 = g_mres[1][batch][lane];
                float m2 = g_mres[2][batch][lane];
                float re = (arv * m0 + brv * m1 + grv * m2) * inv;
                float im = (aiv * m0 + biv * m1 + giv * m2) * inv;
                out[batch * NOUT + lane] = sqrtf(re * re + im * im);
            }
            if (lane == 0) g_cnt[batch] = 0;      // restore for next replay
        }
    }
}

extern "C" void kernel_launch(void* const* d_in, const int* in_sizes, int n_in,
                              void* d_out, int out_size) {
    const float* x      = (const float*)d_in[0];
    const float* W1     = (const float*)d_in[1];
    const float* b1     = (const float*)d_in[2];
    const float* W2     = (const float*)d_in[3];
    const float* b2     = (const float*)d_in[4];
    const float* W3     = (const float*)d_in[5];
    const float* b3     = (const float*)d_in[6];
    const float* base1  = (const float*)d_in[7];
    const float* base2  = (const float*)d_in[8];
    const float* base3  = (const float*)d_in[9];
    const float* ar     = (const float*)d_in[10];
    const float* ai     = (const float*)d_in[11];
    const float* br     = (const float*)d_in[12];
    const float* bi     = (const float*)d_in[13];
    const float* gr     = (const float*)d_in[14];
    const float* gi     = (const float*)d_in[15];
    float* out = (float*)d_out;

    dim3 grid(256, 3);
    qsb_kernel<<<grid, 256>>>(x, W1, b1, W2, b2, W3, b3,
                              base1, base2, base3,
                              ar, ai, br, bi, gr, gi, out);
}

// round 17
// speedup vs baseline: 1.5122x; 1.5122x over previous
#include <cuda_runtime.h>
#include <math.h>

#define NQ 10
#define NP 100
#define FD 256
#define NOUT 30
#define TWO_PI_F 6.2831853071795864769f

// Cross-CTA scratch + per-sample arrival counters (zero-init; the combining
// CTA resets its counter each launch so graph replays see clean state).
__device__ float g_mres[3][256][32];
__device__ int   g_cnt[256];

// Pair barrier for cross-warp exchange on amp-bit b (7/8/9). Partners:
// b=7 -> warp^1, b=8 -> warp^2, b=9 -> warp^4. Disjoint id ranges per bit.
__device__ __forceinline__ void pbar(int b, int warp) {
    int id;
    if (b == 7)      id = 1 + (warp >> 1);
    else if (b == 8) id = 5 + ((warp & 1) | ((warp & 4) >> 1));
    else             id = 9 + (warp & 3);
    asm volatile("bar.sync %0, 64;" :: "r"(id) : "memory");
}

// ---------------------------------------------------------------------------
// One CTA = one (sample, branch). 256 threads, 4 amps/thread.
// amp = (tid << 2) | j : j bits 0-1 local, tid bits 0-4 lane (amp bits 2-6),
// tid bits 5-7 cross-warp (amp bits 7-9, via pair-barrier smem exchange).
// ---------------------------------------------------------------------------

__device__ __forceinline__ void apply_u(int b, float u00r, float u00i,
                                        float u01r, float u01i,
                                        float ar[4], float ai[4],
                                        int tid, int warp, float* B) {
    if (b < 2) {                                  // local register pairs
#pragma unroll
        for (int t = 0; t < 2; t++) {
            int j0 = (b == 0) ? t * 2 : t;
            int j1 = j0 | (1 << b);
            float r0 = ar[j0], i0 = ai[j0], r1 = ar[j1], i1 = ai[j1];
            ar[j0] =  u00r * r0 - u00i * i0 + u01r * r1 - u01i * i1;
            ai[j0] =  u00r * i0 + u00i * r0 + u01r * i1 + u01i * r1;
            ar[j1] = -u01r * r0 - u01i * i0 + u00r * r1 + u00i * i1;
            ai[j1] = -u01r * i0 + u01i * r0 + u00r * i1 - u00i * r1;
        }
    } else if (b < 7) {                           // lane bits: warp shuffle
        const int m = 1 << (b - 2);
        const int s = (tid >> (b - 2)) & 1;
        const float cwr = u00r, cwi = s ? -u00i : u00i;
        const float cpr = s ? -u01r : u01r, cpi = u01i;
#pragma unroll
        for (int j = 0; j < 4; j++) {
            float pr = __shfl_xor_sync(0xffffffffu, ar[j], m);
            float pi = __shfl_xor_sync(0xffffffffu, ai[j], m);
            float orr = ar[j], oii = ai[j];
            ar[j] = cwr * orr - cwi * oii + cpr * pr - cpi * pi;
            ai[j] = cwr * oii + cwi * orr + cpr * pi + cpi * pr;
        }
    } else {                                      // cross-warp bits: smem pair
        const int m = 1 << (b - 2);
        const int s = (tid >> (b - 2)) & 1;
        float4* A4 = (float4*)B;
        float4* I4 = (float4*)(B + 1024);
        A4[tid] = make_float4(ar[0], ar[1], ar[2], ar[3]);
        I4[tid] = make_float4(ai[0], ai[1], ai[2], ai[3]);
        pbar(b, warp);
        float4 pa = A4[tid ^ m];
        float4 pb = I4[tid ^ m];
        const float cwr = u00r, cwi = s ? -u00i : u00i;
        const float cpr = s ? -u01r : u01r, cpi = u01i;
        float prr[4] = {pa.x, pa.y, pa.z, pa.w};
        float pii[4] = {pb.x, pb.y, pb.z, pb.w};
#pragma unroll
        for (int j = 0; j < 4; j++) {
            float orr = ar[j], oii = ai[j];
            ar[j] = cwr * orr - cwi * oii + cpr * prr[j] - cpi * pii[j];
            ai[j] = cwr * oii + cwi * orr + cpr * pii[j] + cpi * prr[j];
        }
        pbar(b, warp);                            // reads done before reuse
    }
}

__device__ __forceinline__ void apply_crx(int pc, int pt, float c, float s,
                                          float ar[4], float ai[4],
                                          int tid, int warp, float* B) {
    const bool tc = (pc >= 2) ? (((tid >> (pc - 2)) & 1) != 0) : true;
    if (pt < 2) {                                 // local target
#pragma unroll
        for (int t = 0; t < 2; t++) {
            int j0 = (pt == 0) ? t * 2 : t;
            int j1 = j0 | (1 << pt);
            bool upd = tc && (pc < 2 ? (((j0 >> pc) & 1) != 0) : true);
            if (upd) {
                float r0 = ar[j0], i0 = ai[j0], r1 = ar[j1], i1 = ai[j1];
                ar[j0] = c * r0 + s * i1;  ai[j0] = c * i0 - s * r1;
                ar[j1] = c * r1 + s * i0;  ai[j1] = c * i1 - s * r0;
            }
        }
    } else if (pt < 7) {                          // lane target: shuffle
        const int m = 1 << (pt - 2);
        if (pc >= 7 && !tc) return;               // warp-uniform control: skip
#pragma unroll
        for (int j = 0; j < 4; j++) {
            float pr = __shfl_xor_sync(0xffffffffu, ar[j], m);
            float pi = __shfl_xor_sync(0xffffffffu, ai[j], m);
            bool upd = tc && (pc < 2 ? (((j >> pc) & 1) != 0) : true);
            if (upd) {
                float orr = ar[j], oii = ai[j];
                ar[j] = c * orr + s * pi;
                ai[j] = c * oii - s * pr;
            }
        }
    } else {                                      // cross-warp target: smem pair
        const int m = 1 << (pt - 2);
        float4* A4 = (float4*)B;
        float4* I4 = (float4*)(B + 1024);
        A4[tid] = make_float4(ar[0], ar[1], ar[2], ar[3]);
        I4[tid] = make_float4(ai[0], ai[1], ai[2], ai[3]);
        pbar(pt, warp);
        float4 pa = A4[tid ^ m];
        float4 pb = I4[tid ^ m];
        float prr[4] = {pa.x, pa.y, pa.z, pa.w};
        float pii[4] = {pb.x, pb.y, pb.z, pb.w};
#pragma unroll
        for (int j = 0; j < 4; j++) {
            bool upd = tc && (pc < 2 ? (((j >> pc) & 1) != 0) : true);
            if (upd) {
                float orr = ar[j], oii = ai[j];
                ar[j] = c * orr + s * pii[j];
                ai[j] = c * oii - s * prr[j];
            }
        }
        pbar(pt, warp);                           // reads done before reuse
    }
}

__global__ __launch_bounds__(256, 6)
void qsb_kernel(const float* __restrict__ x,
                const float* __restrict__ W1, const float* __restrict__ b1,
                const float* __restrict__ W2, const float* __restrict__ b2,
                const float* __restrict__ W3, const float* __restrict__ b3,
                const float* __restrict__ base1, const float* __restrict__ base2,
                const float* __restrict__ base3,
                const float* __restrict__ alpha_r, const float* __restrict__ alpha_i,
                const float* __restrict__ beta_r,  const float* __restrict__ beta_i,
                const float* __restrict__ gamma_r, const float* __restrict__ gamma_i,
                float* __restrict__ out) {
    __shared__ float sx[FD];
    __shared__ float gc[NP], gs[NP];
    __shared__ float ginit[NQ][4];                // col-0 of fused layer-0 U's
    __shared__ float buf[2048];                   // exchange/dump buffer
    __shared__ float sm30[32];                    // per-CTA expectation values

    const int tid   = threadIdx.x;
    const int batch = blockIdx.x;
    const int g     = blockIdx.y;                 // branch 0..2
    const int lane  = tid & 31;
    const int warp  = tid >> 5;

    sx[tid] = x[batch * FD + tid];

    const float* W  = (g == 0) ? W1 : ((g == 1) ? W2 : W3);
    const float* bb = (g == 0) ? b1 : ((g == 1) ? b2 : b3);
    const float* ba = (g == 0) ? base1 : ((g == 1) ? base2 : base3);
    __syncthreads();

    // ---- GEMV (pipelined, warp-per-row, coalesced) + sigmoid ----
    {
        const float4* xv = (const float4*)sx;
        const float4 x0 = xv[lane * 2];
        const float4 x1 = xv[lane * 2 + 1];
        int p = warp;
        const float4* Wv = (const float4*)(W + p * FD);
        float4 w0 = Wv[lane * 2], w1 = Wv[lane * 2 + 1];
        while (p < NP) {
            const int pn = p + 8;
            float4 nw0, nw1;
            if (pn < NP) {
                const float4* Wn = (const float4*)(W + pn * FD);
                nw0 = Wn[lane * 2]; nw1 = Wn[lane * 2 + 1];
            }
            float acc = w0.x * x0.x + w0.y * x0.y + w0.z * x0.z + w0.w * x0.w
                      + w1.x * x1.x + w1.y * x1.y + w1.z * x1.z + w1.w * x1.w;
#pragma unroll
            for (int o = 16; o; o >>= 1)
                acc += __shfl_xor_sync(0xffffffffu, acc, o);
            if (lane == 0) {
                float t     = acc + bb[p] + ba[p];
                float sig   = 1.f / (1.f + __expf(-t));
                float sv, cv;
                __sincosf(0.5f * sig * TWO_PI_F, &sv, &cv);
                gc[p] = cv; gs[p] = sv;
            }
            w0 = nw0; w1 = nw1; p = pn;
        }
    }
    __syncthreads();

    // ---- layer-0 1q sweep folded into product-state init ----
    if (tid < NQ) {
        const int w = tid, i0 = 3 * w;
        float c0 = gc[i0], s0 = gs[i0];
        float c1 = gc[i0 + 1], s1 = gs[i0 + 1];
        float cz = gc[i0 + 2], sz = gs[i0 + 2];
        float u00r =  cz * c1 * c0 + sz * s1 * s0;
        float u00i =  cz * s1 * s0 - sz * c1 * c0;
        float u01r = -(cz * s1 * c0 + sz * c1 * s0);
        float u01i =  sz * s1 * c0 - cz * c1 * s0;
        ginit[9 - w][0] = u00r;   ginit[9 - w][1] = u00i;   // amp|0>
        ginit[9 - w][2] = -u01r;  ginit[9 - w][3] = u01i;   // amp|1> = -conj(u01)
    }
    __syncthreads();

    // ---- init: product state with fwd-ring gates i=0 (p30) and i=1 (p31)
    //      folded in analytically (partner amps are still product values) ----
    float ar[4], ai[4];
    {
        float Rr = 1.f, Ri = 0.f;                 // product over bits {2..6, 9}
#pragma unroll
        for (int p = 2; p < 10; p++) {
            if (p == 7 || p == 8) continue;
            const int bit = (tid >> (p - 2)) & 1;
            float fr = ginit[p][bit * 2];
            float fi = ginit[p][bit * 2 + 1];
            float nr = Rr * fr - Ri * fi;
            float ni = Rr * fi + Ri * fr;
            Rr = nr; Ri = ni;
        }
        const int b7 = (tid >> 5) & 1;
        const int b8 = (tid >> 6) & 1;
        const int b9 = (tid >> 7) & 1;
        float f7r  = ginit[7][b7 * 2],       f7i  = ginit[7][b7 * 2 + 1];
        float f7nr = ginit[7][(1 - b7) * 2], f7ni = ginit[7][(1 - b7) * 2 + 1];
        float f8r  = ginit[8][b8 * 2],       f8i  = ginit[8][b8 * 2 + 1];
        float f8nr = ginit[8][(1 - b8) * 2], f8ni = ginit[8][(1 - b8) * 2 + 1];
        float R7r  = Rr * f7r  - Ri * f7i,   R7i  = Rr * f7i  + Ri * f7r;
        float R7nr = Rr * f7nr - Ri * f7ni,  R7ni = Rr * f7ni + Ri * f7nr;
        float qbr  = R7r  * f8r  - R7i  * f8i,  qbi  = R7r  * f8i  + R7i  * f8r;
        float q8r  = R7r  * f8nr - R7i  * f8ni, q8i  = R7r  * f8ni + R7i  * f8nr;
        float q7r  = R7nr * f8r  - R7ni * f8i,  q7i  = R7nr * f8i  + R7ni * f8r;
        float q78r = R7nr * f8nr - R7ni * f8ni, q78i = R7nr * f8ni + R7ni * f8nr;
        // gate p30: CRX ctrl bit9, tgt bit8 (RX symmetric: a' = c a - i s a_partner)
        float c0g = gc[30], s0g = gs[30];
        float A1br, A1bi, A1fr, A1fi;
        if (b9) {
            A1br = c0g * qbr + s0g * q8i;   A1bi = c0g * qbi - s0g * q8r;
            A1fr = c0g * q7r + s0g * q78i;  A1fi = c0g * q7i - s0g * q78r;
        } else {
            A1br = qbr; A1bi = qbi; A1fr = q7r; A1fi = q7i;
        }
        // gate p31: CRX ctrl bit8, tgt bit7
        float c1g = gc[31], s1g = gs[31];
        float Sr, Si;
        if (b8) { Sr = c1g * A1br + s1g * A1fi; Si = c1g * A1bi - s1g * A1fr; }
        else    { Sr = A1br; Si = A1bi; }
        // expand local bits 0,1
        float h1r0 = ginit[1][0], h1i0 = ginit[1][1];
        float h1r1 = ginit[1][2], h1i1 = ginit[1][3];
        float h0r0 = ginit[0][0], h0i0 = ginit[0][1];
        float h0r1 = ginit[0][2], h0i1 = ginit[0][3];
        float t0r = Sr * h1r0 - Si * h1i0, t0i = Sr * h1i0 + Si * h1r0;
        float t1r = Sr * h1r1 - Si * h1i1, t1i = Sr * h1i1 + Si * h1r1;
        ar[0] = t0r * h0r0 - t0i * h0i0;  ai[0] = t0r * h0i0 + t0i * h0r0;
        ar[1] = t0r * h0r1 - t0i * h0i1;  ai[1] = t0r * h0i1 + t0i * h0r1;
        ar[2] = t1r * h0r0 - t1i * h0i0;  ai[2] = t1r * h0i0 + t1i * h0r0;
        ar[3] = t1r * h0r1 - t1i * h0i1;  ai[3] = t1r * h0i1 + t1i * h0r1;
    }

    // ---- layer 0 rings: fwd i=2..9 (params 32..39), bwd (40..49) ----
    int idx = 32;
#pragma unroll
    for (int i = 2; i < NQ; i++) {
        apply_crx(9 - i, 9 - ((i + 1) % NQ), gc[idx], gs[idx],
                  ar, ai, tid, warp, buf);
        idx++;
    }
    idx = 40;
#pragma unroll
    for (int i = NQ - 1; i >= 0; i--) {
        apply_crx(9 - i, 9 - ((i + 9) % NQ), gc[idx], gs[idx],
                  ar, ai, tid, warp, buf);
        idx++;
    }

    // ---- layer 1 ----
    {
        float c0 = gc[50], s0 = gs[50];
        float c1 = gc[51], s1 = gs[51];
        float cz = gc[52], sz = gs[52];
        float u00r =  cz * c1 * c0 + sz * s1 * s0;
        float u00i =  cz * s1 * s0 - sz * c1 * c0;
        float u01r = -(cz * s1 * c0 + sz * c1 * s0);
        float u01i =  sz * s1 * c0 - cz * c1 * s0;
        apply_u(9, u00r, u00i, u01r, u01i, ar, ai, tid, warp, buf);
    }
    // Fused forward ring: MCRX(w-1, w) absorbing U_w, w=1..9.
#pragma unroll
    for (int w = 1; w <= 9; w++) {
        const int iu = 50 + 3 * w;
        float c0 = gc[iu], s0 = gs[iu];
        float c1 = gc[iu + 1], s1 = gs[iu + 1];
        float cz = gc[iu + 2], sz = gs[iu + 2];
        float u00r =  cz * c1 * c0 + sz * s1 * s0;
        float u00i =  cz * s1 * s0 - sz * c1 * c0;
        float u01r = -(cz * s1 * c0 + sz * c1 * s0);
        float u01i =  sz * s1 * c0 - cz * c1 * s0;
        float cr = gc[79 + w], sr = gs[79 + w];
        float v00r = cr * u00r + sr * u01i;
        float v00i = cr * u00i + sr * u01r;
        float v01r = cr * u01r - sr * u00i;
        float v01i = cr * u01i - sr * u00r;
        const int pc = 10 - w;
        const int pt = 9 - w;
        if (pc >= 2) {
            const bool tc = ((tid >> (pc - 2)) & 1) != 0;
            float m00r = tc ? v00r : u00r;
            float m00i = tc ? v00i : u00i;
            float m01r = tc ? v01r : u01r;
            float m01i = tc ? v01i : u01i;
            apply_u(pt, m00r, m00i, m01r, m01i, ar, ai, tid, warp, buf);
        } else {
            // w=9: pc=1 (local), pt=0 (local): U on pair(0,1), V on pair(2,3)
            {
                float r0 = ar[0], i0 = ai[0], r1 = ar[1], i1 = ai[1];
                ar[0] =  u00r * r0 - u00i * i0 + u01r * r1 - u01i * i1;
                ai[0] =  u00r * i0 + u00i * r0 + u01r * i1 + u01i * r1;
                ar[1] = -u01r * r0 - u01i * i0 + u00r * r1 + u00i * i1;
                ai[1] = -u01r * i0 + u01i * r0 + u00r * i1 - u00i * r1;
            }
            {
                float r0 = ar[2], i0 = ai[2], r1 = ar[3], i1 = ai[3];
                ar[2] =  v00r * r0 - v00i * i0 + v01r * r1 - v01i * i1;
                ai[2] =  v00r * i0 + v00i * r0 + v01r * i1 + v01i * r1;
                ar[3] = -v01r * r0 - v01i * i0 + v00r * r1 + v00i * i1;
                ai[3] = -v01r * i0 + v01i * r0 + v00r * i1 - v00i * r1;
            }
        }
    }
    // Closing forward-ring gate CRX(9, 0): control bit 0, target bit 9.
    apply_crx(0, 9, gc[89], gs[89], ar, ai, tid, warp, buf);
    // Backward ring, params 90..99
    idx = 90;
#pragma unroll
    for (int i = NQ - 1; i >= 0; i--) {
        apply_crx(9 - i, 9 - ((i + 9) % NQ), gc[idx], gs[idx],
                  ar, ai, tid, warp, buf);
        idx++;
    }

    // ---- dump state ----
    {
        float4* A4 = (float4*)buf;
        float4* I4 = (float4*)(buf + 1024);
        A4[tid] = make_float4(ar[0], ar[1], ar[2], ar[3]);
        I4[tid] = make_float4(ai[0], ai[1], ai[2], ai[3]);
        __syncthreads();
    }

    // ---- expectations: warp w handles wires {w, w+8}; vectorized loads ----
    {
        const float4* A4 = (const float4*)buf;
        const float4* I4 = (const float4*)(buf + 1024);
        for (int wq = warp; wq < NQ; wq += 8) {
            const int p = 9 - wq;
            float zr = 0.f, zi = 0.f, pz = 0.f;
            if (p >= 2) {
#pragma unroll
                for (int it = 0; it < 4; it++) {
                    int k  = it * 128 + lane * 4;
                    int i0 = ((k >> p) << (p + 1)) | (k & ((1 << p) - 1));
                    int v0 = i0 >> 2;
                    int v1 = (i0 | (1 << p)) >> 2;
                    float4 r0 = A4[v0], m0 = I4[v0];
                    float4 r1 = A4[v1], m1 = I4[v1];
                    zr += r0.x * r1.x + m0.x * m1.x + r0.y * r1.y + m0.y * m1.y
                        + r0.z * r1.z + m0.z * m1.z + r0.w * r1.w + m0.w * m1.w;
                    zi += r0.x * m1.x - m0.x * r1.x + r0.y * m1.y - m0.y * r1.y
                        + r0.z * m1.z - m0.z * r1.z + r0.w * m1.w - m0.w * r1.w;
                    pz += r0.x * r0.x + m0.x * m0.x - r1.x * r1.x - m1.x * m1.x
                        + r0.y * r0.y + m0.y * m0.y - r1.y * r1.y - m1.y * m1.y
                        + r0.z * r0.z + m0.z * m0.z - r1.z * r1.z - m1.z * m1.z
                        + r0.w * r0.w + m0.w * m0.w - r1.w * r1.w - m1.w * m1.w;
                }
            } else {
#pragma unroll
                for (int it = 0; it < 8; it++) {
                    int t = it * 32 + lane;
                    float4 fr = A4[t], fi = I4[t];
                    if (p == 0) {                 // pairs (x,y), (z,w)
                        zr += fr.x * fr.y + fi.x * fi.y + fr.z * fr.w + fi.z * fi.w;
                        zi += fr.x * fi.y - fi.x * fr.y + fr.z * fi.w - fi.z * fr.w;
                        pz += fr.x * fr.x + fi.x * fi.x - fr.y * fr.y - fi.y * fi.y
                            + fr.z * fr.z + fi.z * fi.z - fr.w * fr.w - fi.w * fi.w;
                    } else {                      // p==1: pairs (x,z), (y,w)
                        zr += fr.x * fr.z + fi.x * fi.z + fr.y * fr.w + fi.y * fi.w;
                        zi += fr.x * fi.z - fi.x * fr.z + fr.y * fi.w - fi.y * fr.w;
                        pz += fr.x * fr.x + fi.x * fi.x - fr.z * fr.z - fi.z * fi.z
                            + fr.y * fr.y + fi.y * fi.y - fr.w * fr.w - fi.w * fi.w;
                    }
                }
            }
#pragma unroll
            for (int o = 16; o; o >>= 1) {
                zr += __shfl_xor_sync(0xffffffffu, zr, o);
                zi += __shfl_xor_sync(0xffffffffu, zi, o);
                pz += __shfl_xor_sync(0xffffffffu, pz, o);
            }
            if (lane == 0) {
                sm30[wq]          = 2.f * zr;
                sm30[NQ + wq]     = 2.f * zi;
                sm30[2 * NQ + wq] = pz;
            }
        }
    }
    __syncthreads();

    // ---- tail: warp 0 only. store -> release fence -> atomic -> combine ----
    if (warp == 0) {
        if (lane < NOUT) g_mres[g][batch][lane] = sm30[lane];
        __syncwarp();
        __threadfence();                          // release (1 warp only)
        int old = 0;
        if (lane == 0) old = atomicAdd(&g_cnt[batch], 1);
        old = __shfl_sync(0xffffffffu, old, 0);
        if (old == 2) {                           // last branch: combine
            __threadfence();                      // acquire (1 warp only)
            if (lane < NOUT) {
                float arv = alpha_r[0], aiv = alpha_i[0];
                float brv = beta_r[0],  biv = beta_i[0];
                float grv = gamma_r[0], giv = gamma_i[0];
                float nrm = sqrtf(arv * arv + aiv * aiv + brv * brv +
                                  biv * biv + grv * grv + giv * giv + 1e-9f);
                float inv = 1.f / nrm;
                float m0 = g_mres[0][batch][lane];
                float m1 = g_mres[1][batch][lane];
                float m2 = g_mres[2][batch][lane];
                float re = (arv * m0 + brv * m1 + grv * m2) * inv;
                float im = (aiv * m0 + biv * m1 + giv * m2) * inv;
                out[batch * NOUT + lane] = sqrtf(re * re + im * im);
            }
            if (lane == 0) g_cnt[batch] = 0;      // restore for next replay
        }
    }
}

extern "C" void kernel_launch(void* const* d_in, const int* in_sizes, int n_in,
                              void* d_out, int out_size) {
    const float* x      = (const float*)d_in[0];
    const float* W1     = (const float*)d_in[1];
    const float* b1     = (const float*)d_in[2];
    const float* W2     = (const float*)d_in[3];
    const float* b2     = (const float*)d_in[4];
    const float* W3     = (const float*)d_in[5];
    const float* b3     = (const float*)d_in[6];
    const float* base1  = (const float*)d_in[7];
    const float* base2  = (const float*)d_in[8];
    const float* base3  = (const float*)d_in[9];
    const float* ar     = (const float*)d_in[10];
    const float* ai     = (const float*)d_in[11];
    const float* br     = (const float*)d_in[12];
    const float* bi     = (const float*)d_in[13];
    const float* gr     = (const float*)d_in[14];
    const float* gi     = (const float*)d_in[15];
    float* out = (float*)d_out;

    dim3 grid(256, 3);
    qsb_kernel<<<grid, 256>>>(x, W1, b1, W2, b2, W3, b3,
                              base1, base2, base3,
                              ar, ai, br, bi, gr, gi, out);
}